// round 12
// baseline (speedup 1.0000x reference)
#include <cuda_runtime.h>

// ---------------------------------------------------------------------------
// VoxelBackBone8x decoder: 8 x (masked 27-tap gather conv -> BN -> ReLU)
// fp32 f32x2 packed FMA. Single-buffered tap loop (cross-block overlap hides
// tap-boundary latency), pre-duplicated weights in smem (zero pack MOVs in
// the GEMM inner loop), BN+ReLU fused into the next layer's gather.
// ---------------------------------------------------------------------------

#define NT 256

#define MAXN 110000
__device__ float g_bufA[MAXN * 64];
__device__ float g_bufB[MAXN * 64];
__device__ float g_sum[8 * 64];
__device__ float g_sq [8 * 64];

__device__ __forceinline__ float lo2(unsigned long long v) { return __uint_as_float((unsigned)v); }
__device__ __forceinline__ float hi2(unsigned long long v) { return __uint_as_float((unsigned)(v >> 32)); }
__device__ __forceinline__ void ffma2(unsigned long long& d, unsigned long long a,
                                      unsigned long long b) {
    asm("fma.rn.f32x2 %0, %1, %2, %0;" : "+l"(d) : "l"(a), "l"(b));
}

__global__ void zero_stats_kernel() {
    for (int i = threadIdx.x; i < 8 * 64; i += blockDim.x) {
        g_sum[i] = 0.f;
        g_sq[i]  = 0.f;
    }
}

// ---------------------------------------------------------------------------
// Tiled gather-conv with fused input-BN and fused BN-stat reduction.
//   out[N, CO] = sum_t gather_t( bn(fin) )[N, CI] @ W[t, CI, CO]
// RB rows per block. Weights staged per tap into smem DUPLICATED
// (Wd[k][2c] = Wd[k][2c+1] = W[k][c]) so the f32x2 B-operand is a direct
// 16B shared load (no register duplication MOVs).
// ---------------------------------------------------------------------------
template <int CI, int CO, int RB, bool BN>
__global__ void __launch_bounds__(NT, 3) conv_kernel(
    const float* __restrict__ fin, const int* __restrict__ nbr,
    const float* __restrict__ W, float* __restrict__ fout,
    float* __restrict__ sumP, float* __restrict__ sqP, int N,
    const float* __restrict__ pSum, const float* __restrict__ pSq,
    const float* __restrict__ pG, const float* __restrict__ pB, int pN)
{
    constexpr int TN = 4;
    constexpr int BX = CO / TN;        // threads along columns
    constexpr int BY = NT / BX;        // threads along rows
    constexpr int TM = RB / BY;        // rows per thread (8 or 4)
    constexpr int NP = TM / 2;         // f32x2 row-pairs per thread
    constexpr int TPR = NT / RB;       // gather threads per row (1 or 2)
    constexpr int CPT = CI / (4 * TPR);// float4 chunks per gather thread
    constexpr int WHALF = CI * CO / 2; // float2 elements of W per tap

    extern __shared__ float smem[];
    float* featT = smem;                      // CI * RB   (transposed [k][row])
    float* Wd    = featT + CI * RB;           // CI * 2*CO (duplicated)
    float* aS    = Wd + CI * 2 * CO;          // CI
    float* bS    = aS + CI;                   // CI
    float* ssum  = bS + CI;                   // CO
    float* ssq   = ssum + CO;                 // CO

    const int tid  = threadIdx.x;
    const int row0 = blockIdx.x * RB;

    if (BN && tid < CI) {
        const float mu  = pSum[tid] / (float)pN;
        const float var = pSq[tid] / (float)pN - mu * mu;
        const float a   = pG[tid] * rsqrtf(var + 1e-3f);
        aS[tid] = a;
        bS[tid] = pB[tid] - mu * a;
    }
    for (int i = tid; i < 2 * CO; i += NT) ssum[i] = 0.f;

    const int grow = (TPR == 2) ? (tid & (RB - 1)) : tid;
    const int gh   = (TPR == 2) ? (tid >> 7) : 0;
    const bool grow_ok = (row0 + grow) < N;
    const int* nrow = nbr + (long)(row0 + grow) * 27;

    const int tx = tid % BX, ty = tid / BX;
    const int c0 = tx * TN, r0 = ty * TM;

    unsigned long long acc[NP][TN];
#pragma unroll
    for (int p = 0; p < NP; p++)
#pragma unroll
        for (int c = 0; c < TN; c++) acc[p][c] = 0ull;

    __syncthreads();   // aS/bS + ssum ready

    // ---- helper: gather one tap's features (BN+ReLU fused) into featT ----
    auto gather = [&](int j) {
#pragma unroll
        for (int cc = 0; cc < CPT; cc++) {
            const int ch = gh * CPT + cc;
            float4 v = make_float4(0.f, 0.f, 0.f, 0.f);
            if (j >= 0) {
                v = __ldg(reinterpret_cast<const float4*>(fin) + j * (CI / 4) + ch);
                if (BN) {
                    const float4 a4 = *reinterpret_cast<const float4*>(&aS[ch * 4]);
                    const float4 b4 = *reinterpret_cast<const float4*>(&bS[ch * 4]);
                    v.x = fmaxf(fmaf(v.x, a4.x, b4.x), 0.f);
                    v.y = fmaxf(fmaf(v.y, a4.y, b4.y), 0.f);
                    v.z = fmaxf(fmaf(v.z, a4.z, b4.z), 0.f);
                    v.w = fmaxf(fmaf(v.w, a4.w, b4.w), 0.f);
                }
            }
            const int k = ch * 4;
            featT[(k + 0) * RB + grow] = v.x;
            featT[(k + 1) * RB + grow] = v.y;
            featT[(k + 2) * RB + grow] = v.z;
            featT[(k + 3) * RB + grow] = v.w;
        }
    };
    auto stage_w = [&](int t) {
        const float2* wg = reinterpret_cast<const float2*>(W + t * CI * CO);
        for (int i = tid; i < WHALF; i += NT) {
            const float2 w = __ldg(wg + i);
            reinterpret_cast<float4*>(Wd)[i] = make_float4(w.x, w.x, w.y, w.y);
        }
    };

    // ---- prologue: stage tap 0 ----
    stage_w(0);
    gather(grow_ok ? __ldg(nrow + 0) : -1);
    __syncthreads();

    // ---- tap loop ----
    const float* fbase = featT + r0;
    for (int t = 0; t < 27; t++) {
        int jn = -1;
        if (t < 26 && grow_ok) jn = __ldg(nrow + t + 1);  // prefetch next index

        // GEMM: acc += featT[:, rows]^T * W[t]
#pragma unroll 4
        for (int k = 0; k < CI; k++) {
            const ulonglong2* fr =
                reinterpret_cast<const ulonglong2*>(fbase + k * RB);
            const ulonglong2* wr =
                reinterpret_cast<const ulonglong2*>(&Wd[k * 2 * CO + 2 * c0]);
            const ulonglong2 w01 = wr[0];
            const ulonglong2 w23 = wr[1];
            if constexpr (TM == 8) {
                const ulonglong2 f01 = fr[0];
                const ulonglong2 f23 = fr[1];
                ffma2(acc[0][0], f01.x, w01.x); ffma2(acc[0][1], f01.x, w01.y);
                ffma2(acc[0][2], f01.x, w23.x); ffma2(acc[0][3], f01.x, w23.y);
                ffma2(acc[1][0], f01.y, w01.x); ffma2(acc[1][1], f01.y, w01.y);
                ffma2(acc[1][2], f01.y, w23.x); ffma2(acc[1][3], f01.y, w23.y);
                ffma2(acc[2][0], f23.x, w01.x); ffma2(acc[2][1], f23.x, w01.y);
                ffma2(acc[2][2], f23.x, w23.x); ffma2(acc[2][3], f23.x, w23.y);
                ffma2(acc[3][0], f23.y, w01.x); ffma2(acc[3][1], f23.y, w01.y);
                ffma2(acc[3][2], f23.y, w23.x); ffma2(acc[3][3], f23.y, w23.y);
            } else {  // TM == 4
                const ulonglong2 f01 = fr[0];
                ffma2(acc[0][0], f01.x, w01.x); ffma2(acc[0][1], f01.x, w01.y);
                ffma2(acc[0][2], f01.x, w23.x); ffma2(acc[0][3], f01.x, w23.y);
                ffma2(acc[1][0], f01.y, w01.x); ffma2(acc[1][1], f01.y, w01.y);
                ffma2(acc[1][2], f01.y, w23.x); ffma2(acc[1][3], f01.y, w23.y);
            }
        }

        if (t < 26) {
            __syncthreads();          // all warps done reading featT / Wd
            gather(jn);
            stage_w(t + 1);
            __syncthreads();          // next tap staged
        }
    }

    // ---- epilogue: write y (pre-BN) + accumulate BN stats ----
    float psum[TN] = {0.f, 0.f, 0.f, 0.f};
    float psq [TN] = {0.f, 0.f, 0.f, 0.f};
#pragma unroll
    for (int p = 0; p < NP; p++) {
#pragma unroll
        for (int e = 0; e < 2; e++) {
            const int gr = row0 + r0 + 2 * p + e;
            if (gr < N) {
                float v[TN];
#pragma unroll
                for (int c = 0; c < TN; c++)
                    v[c] = e ? hi2(acc[p][c]) : lo2(acc[p][c]);
                *reinterpret_cast<float4*>(&fout[(long)gr * CO + c0]) =
                    make_float4(v[0], v[1], v[2], v[3]);
#pragma unroll
                for (int c = 0; c < TN; c++) {
                    psum[c] += v[c];
                    psq[c]  += v[c] * v[c];
                }
            }
        }
    }
#pragma unroll
    for (int c = 0; c < TN; c++) {
        atomicAdd(&ssum[c0 + c], psum[c]);
        atomicAdd(&ssq [c0 + c], psq[c]);
    }
    __syncthreads();
    if (tid < CO) {
        atomicAdd(&sumP[tid], ssum[tid]);
        atomicAdd(&sqP [tid], ssq[tid]);
    }
}

// ---------------------------------------------------------------------------
// Final 16 -> 3 conv, fused input-BN(m1): one thread per row.
// ---------------------------------------------------------------------------
__global__ void __launch_bounds__(256) conv_c5_kernel(
    const float* __restrict__ fin, const int* __restrict__ nbr,
    const float* __restrict__ W, float* __restrict__ fout,
    float* __restrict__ sumP, float* __restrict__ sqP, int N,
    const float* __restrict__ pSum, const float* __restrict__ pSq,
    const float* __restrict__ pG, const float* __restrict__ pB, int pN)
{
    __shared__ float Ws[27 * 16 * 3];
    __shared__ float aSh[16], bSh[16];
    __shared__ float ss[6];
    const int tid = threadIdx.x;
    for (int i = tid; i < 27 * 48; i += 256) Ws[i] = W[i];
    if (tid < 16) {
        const float mu  = pSum[tid] / (float)pN;
        const float var = pSq[tid] / (float)pN - mu * mu;
        const float a   = pG[tid] * rsqrtf(var + 1e-3f);
        aSh[tid] = a;
        bSh[tid] = pB[tid] - mu * a;
    }
    if (tid < 6) ss[tid] = 0.f;
    __syncthreads();

    float areg[16], breg[16];
#pragma unroll
    for (int k = 0; k < 16; k++) { areg[k] = aSh[k]; breg[k] = bSh[k]; }

    const int row = blockIdx.x * 256 + tid;
    float a0 = 0.f, a1 = 0.f, a2 = 0.f;
    if (row < N) {
        for (int t = 0; t < 27; t++) {
            const int j = nbr[row * 27 + t];
            if (j >= 0) {
                const float4* fr = reinterpret_cast<const float4*>(fin + j * 16);
                float f[16];
                float4 q;
                q = fr[0]; f[0] = q.x; f[1] = q.y; f[2]  = q.z; f[3]  = q.w;
                q = fr[1]; f[4] = q.x; f[5] = q.y; f[6]  = q.z; f[7]  = q.w;
                q = fr[2]; f[8] = q.x; f[9] = q.y; f[10] = q.z; f[11] = q.w;
                q = fr[3]; f[12] = q.x; f[13] = q.y; f[14] = q.z; f[15] = q.w;
#pragma unroll
                for (int k = 0; k < 16; k++) {
                    const float v = fmaxf(fmaf(f[k], areg[k], breg[k]), 0.f);
                    const float* wp = &Ws[(t * 16 + k) * 3];
                    a0 += v * wp[0];
                    a1 += v * wp[1];
                    a2 += v * wp[2];
                }
            }
        }
        fout[row * 3 + 0] = a0;
        fout[row * 3 + 1] = a1;
        fout[row * 3 + 2] = a2;
    }
    atomicAdd(&ss[0], a0); atomicAdd(&ss[1], a1); atomicAdd(&ss[2], a2);
    atomicAdd(&ss[3], a0 * a0); atomicAdd(&ss[4], a1 * a1); atomicAdd(&ss[5], a2 * a2);
    __syncthreads();
    if (tid < 3) {
        atomicAdd(&sumP[tid], ss[tid]);
        atomicAdd(&sqP [tid], ss[3 + tid]);
    }
}

// ---------------------------------------------------------------------------
// BN apply (final layer only, no relu) -> d_out
// ---------------------------------------------------------------------------
__global__ void normalize_kernel(const float* __restrict__ in, float* __restrict__ out,
                                 int N, int C, const float* __restrict__ g,
                                 const float* __restrict__ b,
                                 const float* __restrict__ sum,
                                 const float* __restrict__ sq)
{
    extern __shared__ float s[];
    if (threadIdx.x < C) {
        const float mu  = sum[threadIdx.x] / (float)N;
        const float var = sq[threadIdx.x] / (float)N - mu * mu;
        const float a   = g[threadIdx.x] * rsqrtf(var + 1e-3f);
        s[threadIdx.x]     = a;
        s[C + threadIdx.x] = b[threadIdx.x] - mu * a;
    }
    __syncthreads();
    const int total  = N * C;
    const int stride = gridDim.x * blockDim.x;
    for (int i = blockIdx.x * blockDim.x + threadIdx.x; i < total; i += stride) {
        const int c = i % C;
        out[i] = in[i] * s[c] + s[C + c];
    }
}

// ---------------------------------------------------------------------------

static inline int conv_smem(int CI, int CO, int RB) {
    return (CI * RB + 2 * CI * CO + 2 * CI + 2 * CO) * 4;
}

extern "C" void kernel_launch(void* const* d_in, const int* in_sizes, int n_in,
                              void* d_out, int out_size)
{
    (void)n_in;
    // Detect input ordering: signature order (x first) vs dict order (x at 7).
    const long s0 = in_sizes[0], s1 = in_sizes[1];
    const bool sig = (s0 % 64 == 0) && (s1 % 27 == 0) && (s0 / 64 == s1 / 27);

    const float* x;
    const int* NB[7];   // nbr4, inv43, nbr3, inv32, nbr2, inv21, nbr1
    if (sig) {
        x = (const float*)d_in[0];
        for (int i = 0; i < 7; i++) NB[i] = (const int*)d_in[1 + i];
    } else {
        x = (const float*)d_in[7];
        for (int i = 0; i < 7; i++) NB[i] = (const int*)d_in[i];
    }
    const int n4 = (sig ? in_sizes[0] : in_sizes[7]) / 64;
    const int n3 = (sig ? in_sizes[2] : in_sizes[1]) / 27;  // inv43 rows
    const int n2 = (sig ? in_sizes[4] : in_sizes[3]) / 27;  // inv32 rows
    const int n1 = out_size / 3;

    const float *Wp[8], *Gp[8], *Bp[8];
    for (int i = 0; i < 8; i++) {
        Wp[i] = (const float*)d_in[8 + 3 * i];
        Gp[i] = (const float*)d_in[9 + 3 * i];
        Bp[i] = (const float*)d_in[10 + 3 * i];
    }

    float *bufA, *bufB, *sums, *sqs;
    cudaGetSymbolAddress((void**)&bufA, g_bufA);
    cudaGetSymbolAddress((void**)&bufB, g_bufB);
    cudaGetSymbolAddress((void**)&sums, g_sum);
    cudaGetSymbolAddress((void**)&sqs,  g_sq);

    const int smA = conv_smem(64, 64, 128);
    const int smB = conv_smem(64, 32, 128);
    const int smC = conv_smem(32, 32, 256);
    const int smD = conv_smem(32, 16, 256);
    const int smE = conv_smem(16, 16, 256);
    cudaFuncSetAttribute(conv_kernel<64, 64, 128, false>, cudaFuncAttributeMaxDynamicSharedMemorySize, smA);
    cudaFuncSetAttribute(conv_kernel<64, 64, 128, true >, cudaFuncAttributeMaxDynamicSharedMemorySize, smA);
    cudaFuncSetAttribute(conv_kernel<64, 32, 128, true >, cudaFuncAttributeMaxDynamicSharedMemorySize, smB);
    cudaFuncSetAttribute(conv_kernel<32, 32, 256, true >, cudaFuncAttributeMaxDynamicSharedMemorySize, smC);
    cudaFuncSetAttribute(conv_kernel<32, 16, 256, true >, cudaFuncAttributeMaxDynamicSharedMemorySize, smD);
    cudaFuncSetAttribute(conv_kernel<16, 16, 256, true >, cudaFuncAttributeMaxDynamicSharedMemorySize, smE);

    auto g128 = [](int n) { return (n + 127) / 128; };
    auto g256 = [](int n) { return (n + 255) / 256; };
    auto nblk = [](int total) {
        int b = (total + 255) / 256;
        return b > 16384 ? 16384 : b;
    };

    zero_stats_kernel<<<1, 256>>>();

    // L1: m4 (raw x: n4 x 64 -> bufA, stats[0])
    conv_kernel<64, 64, 128, false><<<g128(n4), NT, smA>>>(
        x, NB[0], Wp[0], bufA, sums + 0, sqs + 0, n4,
        nullptr, nullptr, nullptr, nullptr, 1);
    // L2: i4 (bn0(bufA)[n4] -> bufB: n3 x 64, stats[1])
    conv_kernel<64, 64, 128, true><<<g128(n3), NT, smA>>>(
        bufA, NB[1], Wp[1], bufB, sums + 64, sqs + 64, n3,
        sums + 0, sqs + 0, Gp[0], Bp[0], n4);
    // L3: m3 (bn1(bufB) -> bufA: n3 x 64, stats[2])
    conv_kernel<64, 64, 128, true><<<g128(n3), NT, smA>>>(
        bufB, NB[2], Wp[2], bufA, sums + 128, sqs + 128, n3,
        sums + 64, sqs + 64, Gp[1], Bp[1], n3);
    // L4: i3 (bn2(bufA)[n3] -> bufB: n2 x 32, stats[3])
    conv_kernel<64, 32, 128, true><<<g128(n2), NT, smB>>>(
        bufA, NB[3], Wp[3], bufB, sums + 192, sqs + 192, n2,
        sums + 128, sqs + 128, Gp[2], Bp[2], n3);
    // L5: m2 (bn3(bufB) -> bufA: n2 x 32, stats[4])
    conv_kernel<32, 32, 256, true><<<g256(n2), NT, smC>>>(
        bufB, NB[4], Wp[4], bufA, sums + 256, sqs + 256, n2,
        sums + 192, sqs + 192, Gp[3], Bp[3], n2);
    // L6: i2 (bn4(bufA)[n2] -> bufB: n1 x 16, stats[5])
    conv_kernel<32, 16, 256, true><<<g256(n1), NT, smD>>>(
        bufA, NB[5], Wp[5], bufB, sums + 320, sqs + 320, n1,
        sums + 256, sqs + 256, Gp[4], Bp[4], n2);
    // L7: m1 (bn5(bufB) -> bufA: n1 x 16, stats[6])
    conv_kernel<16, 16, 256, true><<<g256(n1), NT, smE>>>(
        bufB, NB[6], Wp[6], bufA, sums + 384, sqs + 384, n1,
        sums + 320, sqs + 320, Gp[5], Bp[5], n1);
    // L8: c5 (bn6(bufA) -> bufB: n1 x 3, stats[7])
    conv_c5_kernel<<<g256(n1), 256>>>(
        bufA, NB[6], Wp[7], bufB, sums + 448, sqs + 448, n1,
        sums + 384, sqs + 384, Gp[6], Bp[6], n1);
    // Final BN (no relu) -> d_out
    normalize_kernel<<<nblk(n1 * 3), 256, 2 * 3 * 4>>>(
        bufB, (float*)d_out, n1, 3, Gp[7], Bp[7], sums + 448, sqs + 448);
}

// round 15
// speedup vs baseline: 1.5478x; 1.5478x over previous
#include <cuda_runtime.h>

// ---------------------------------------------------------------------------
// VoxelBackBone8x decoder: 8 x (masked 27-tap gather conv -> BN -> ReLU)
// fp32 f32x2 FMA. CI=64 layers: TN=2/TM=16 tiling with pre-duplicated
// weights in smem (conflict-free 16B/lane B loads, broadcast A loads, zero
// pack MOVs). BN+ReLU fused into the next layer's gather; BN stats fused
// into the conv epilogue.
// ---------------------------------------------------------------------------

#define NT 256
#define MAXN 110000
__device__ float g_bufA[MAXN * 64];
__device__ float g_bufB[MAXN * 64];
__device__ float g_sum[8 * 64];
__device__ float g_sq [8 * 64];

__device__ __forceinline__ unsigned long long pack2(float lo, float hi) {
    return ((unsigned long long)__float_as_uint(hi) << 32) |
           (unsigned long long)__float_as_uint(lo);
}
__device__ __forceinline__ float lo2(unsigned long long v) { return __uint_as_float((unsigned)v); }
__device__ __forceinline__ float hi2(unsigned long long v) { return __uint_as_float((unsigned)(v >> 32)); }
__device__ __forceinline__ void ffma2(unsigned long long& d, unsigned long long a,
                                      unsigned long long b) {
    asm("fma.rn.f32x2 %0, %1, %2, %0;" : "+l"(d) : "l"(a), "l"(b));
}

__global__ void zero_stats_kernel() {
    for (int i = threadIdx.x; i < 8 * 64; i += blockDim.x) {
        g_sum[i] = 0.f;
        g_sq[i]  = 0.f;
    }
}

// ---------------------------------------------------------------------------
// Big-layer conv: CI = 64, CO in {64, 32}, 128 rows/block.
// TN=2 columns/thread, TM=16 (CO=64) or 8 (CO=32) rows/thread.
// Weights staged per tap into smem DUPLICATED as f32x2 pairs:
//   Wd[k][4*c2 .. 4*c2+3] = { w[2c2], w[2c2], w[2c2+1], w[2c2+1] }
// so lane tx reads its two duplicated column-pairs as ONE contiguous 16B LDS.
// ---------------------------------------------------------------------------
template <int CO, bool BN>
__global__ void __launch_bounds__(NT, 3) conv_big(
    const float* __restrict__ fin, const int* __restrict__ nbr,
    const float* __restrict__ W, float* __restrict__ fout,
    float* __restrict__ sumP, float* __restrict__ sqP, int N,
    const float* __restrict__ pSum, const float* __restrict__ pSq,
    const float* __restrict__ pG, const float* __restrict__ pB, int pN)
{
    constexpr int CI = 64;
    constexpr int RB = 128;
    constexpr int BX = CO / 2;        // 32 or 16 threads along columns
    constexpr int BY = NT / BX;       // 8 or 16 thread-rows
    constexpr int TM = RB / BY;       // 16 or 8 rows per thread
    constexpr int NP = TM / 2;        // 8 or 4 f32x2 row-pairs
    constexpr int WHALF = CI * CO / 2;

    extern __shared__ float smem[];
    float* featT = smem;                      // CI * RB  (transposed [k][row])
    float* Wd    = featT + CI * RB;           // CI * 2*CO (duplicated)
    float* aS    = Wd + CI * 2 * CO;          // CI
    float* bS    = aS + CI;                   // CI
    float* ssum  = bS + CI;                   // CO
    float* ssq   = ssum + CO;                 // CO

    const int tid  = threadIdx.x;
    const int row0 = blockIdx.x * RB;

    if (BN && tid < CI) {
        const float mu  = pSum[tid] / (float)pN;
        const float var = pSq[tid] / (float)pN - mu * mu;
        const float a   = pG[tid] * rsqrtf(var + 1e-3f);
        aS[tid] = a;
        bS[tid] = pB[tid] - mu * a;
    }
    for (int i = tid; i < 2 * CO; i += NT) ssum[i] = 0.f;

    const int grow = tid & (RB - 1);          // 2 threads per row
    const int gh   = tid >> 7;                // channel half
    const bool gok = (row0 + grow) < N;
    const int* nrow = nbr + (long)(row0 + grow) * 27;

    const int tx = tid % BX, ty = tid / BX;
    const int c0 = tx * 2, r0 = ty * TM;

    unsigned long long acc[NP][2];
#pragma unroll
    for (int p = 0; p < NP; p++) { acc[p][0] = 0ull; acc[p][1] = 0ull; }

    __syncthreads();   // aS/bS + ssum ready

    auto gather = [&](int j) {
#pragma unroll
        for (int cc = 0; cc < 8; cc++) {
            const int ch = gh * 8 + cc;       // float4 chunk 0..15
            float4 v = make_float4(0.f, 0.f, 0.f, 0.f);
            if (j >= 0) {
                v = __ldg(reinterpret_cast<const float4*>(fin) + (long)j * 16 + ch);
                if (BN) {
                    const float4 a4 = *reinterpret_cast<const float4*>(&aS[ch * 4]);
                    const float4 b4 = *reinterpret_cast<const float4*>(&bS[ch * 4]);
                    v.x = fmaxf(fmaf(v.x, a4.x, b4.x), 0.f);
                    v.y = fmaxf(fmaf(v.y, a4.y, b4.y), 0.f);
                    v.z = fmaxf(fmaf(v.z, a4.z, b4.z), 0.f);
                    v.w = fmaxf(fmaf(v.w, a4.w, b4.w), 0.f);
                }
            }
            const int k = ch * 4;
            featT[(k + 0) * RB + grow] = v.x;
            featT[(k + 1) * RB + grow] = v.y;
            featT[(k + 2) * RB + grow] = v.z;
            featT[(k + 3) * RB + grow] = v.w;
        }
    };
    auto stage_w = [&](int t) {
        const float2* wg = reinterpret_cast<const float2*>(W + (long)t * CI * CO);
        for (int i = tid; i < WHALF; i += NT) {
            const float2 w = __ldg(wg + i);
            reinterpret_cast<float4*>(Wd)[i] = make_float4(w.x, w.x, w.y, w.y);
        }
    };

    int jcur = gok ? __ldg(nrow) : -1;
    const float* fbase = featT + r0;

    for (int t = 0; t < 27; t++) {
        const int jn = (t < 26 && gok) ? __ldg(nrow + t + 1) : -1;
        gather(jcur);
        stage_w(t);
        __syncthreads();

#pragma unroll 4
        for (int k = 0; k < CI; k++) {
            const ulonglong2* fr =
                reinterpret_cast<const ulonglong2*>(fbase + k * RB);
            // one contiguous 16B weight load: both duplicated column pairs
            const ulonglong2 wb =
                *reinterpret_cast<const ulonglong2*>(&Wd[k * 2 * CO + 2 * c0]);
            if constexpr (TM == 16) {
                const ulonglong2 f0 = fr[0];
                const ulonglong2 f1 = fr[1];
                const ulonglong2 f2 = fr[2];
                const ulonglong2 f3 = fr[3];
                ffma2(acc[0][0], f0.x, wb.x); ffma2(acc[0][1], f0.x, wb.y);
                ffma2(acc[1][0], f0.y, wb.x); ffma2(acc[1][1], f0.y, wb.y);
                ffma2(acc[2][0], f1.x, wb.x); ffma2(acc[2][1], f1.x, wb.y);
                ffma2(acc[3][0], f1.y, wb.x); ffma2(acc[3][1], f1.y, wb.y);
                ffma2(acc[4][0], f2.x, wb.x); ffma2(acc[4][1], f2.x, wb.y);
                ffma2(acc[5][0], f2.y, wb.x); ffma2(acc[5][1], f2.y, wb.y);
                ffma2(acc[6][0], f3.x, wb.x); ffma2(acc[6][1], f3.x, wb.y);
                ffma2(acc[7][0], f3.y, wb.x); ffma2(acc[7][1], f3.y, wb.y);
            } else {  // TM == 8
                const ulonglong2 f0 = fr[0];
                const ulonglong2 f1 = fr[1];
                ffma2(acc[0][0], f0.x, wb.x); ffma2(acc[0][1], f0.x, wb.y);
                ffma2(acc[1][0], f0.y, wb.x); ffma2(acc[1][1], f0.y, wb.y);
                ffma2(acc[2][0], f1.x, wb.x); ffma2(acc[2][1], f1.x, wb.y);
                ffma2(acc[3][0], f1.y, wb.x); ffma2(acc[3][1], f1.y, wb.y);
            }
        }

        if (t < 26) __syncthreads();
        jcur = jn;
    }

    // ---- epilogue: write y (pre-BN) + fused BN stats ----
    float psum[2] = {0.f, 0.f};
    float psq [2] = {0.f, 0.f};
#pragma unroll
    for (int p = 0; p < NP; p++) {
#pragma unroll
        for (int e = 0; e < 2; e++) {
            const int gr = row0 + r0 + 2 * p + e;
            if (gr < N) {
                const float v0 = e ? hi2(acc[p][0]) : lo2(acc[p][0]);
                const float v1 = e ? hi2(acc[p][1]) : lo2(acc[p][1]);
                *reinterpret_cast<float2*>(&fout[(long)gr * CO + c0]) =
                    make_float2(v0, v1);
                psum[0] += v0; psum[1] += v1;
                psq[0]  += v0 * v0; psq[1] += v1 * v1;
            }
        }
    }
    atomicAdd(&ssum[c0 + 0], psum[0]);
    atomicAdd(&ssum[c0 + 1], psum[1]);
    atomicAdd(&ssq [c0 + 0], psq[0]);
    atomicAdd(&ssq [c0 + 1], psq[1]);
    __syncthreads();
    if (tid < CO) {
        atomicAdd(&sumP[tid], ssum[tid]);
        atomicAdd(&sqP [tid], ssq[tid]);
    }
}

// ---------------------------------------------------------------------------
// Small-layer conv (proven 2091-us structure + fused input-BN + fused stats).
// ---------------------------------------------------------------------------
#define ROWS 128
#define FSTR 132

template <int CI, int CO>
__global__ void __launch_bounds__(NT) conv_small(
    const float* __restrict__ fin, const int* __restrict__ nbr,
    const float* __restrict__ W, float* __restrict__ fout,
    float* __restrict__ sumP, float* __restrict__ sqP, int N,
    const float* __restrict__ pSum, const float* __restrict__ pSq,
    const float* __restrict__ pG, const float* __restrict__ pB, int pN)
{
    constexpr int TN = 4;
    constexpr int BX = CO / TN;
    constexpr int BY = NT / BX;
    constexpr int TM = ROWS / BY;
    constexpr int NP = TM / 2;

    extern __shared__ float smf[];
    float* featT = smf;                           // CI * FSTR
    float* Wt    = featT + CI * FSTR;             // CI * CO
    float* aS    = Wt + CI * CO;                  // CI
    float* bS    = aS + CI;                       // CI
    float* ssum  = bS + CI;                       // CO
    float* ssq   = ssum + CO;                     // CO
    int*   jsm   = (int*)(ssq + CO);              // ROWS * 27

    const int tid  = threadIdx.x;
    const int row0 = blockIdx.x * ROWS;
    int nvalid = N - row0;
    if (nvalid > ROWS) nvalid = ROWS;

    if (tid < CI) {
        const float mu  = pSum[tid] / (float)pN;
        const float var = pSq[tid] / (float)pN - mu * mu;
        const float a   = pG[tid] * rsqrtf(var + 1e-3f);
        aS[tid] = a;
        bS[tid] = pB[tid] - mu * a;
    }
    for (int i = tid; i < 2 * CO; i += NT) ssum[i] = 0.f;
    for (int i = tid; i < ROWS * 27; i += NT)
        jsm[i] = (i < nvalid * 27) ? nbr[(long)row0 * 27 + i] : -1;

    unsigned long long acc[NP][TN];
#pragma unroll
    for (int p = 0; p < NP; p++)
#pragma unroll
        for (int c = 0; c < TN; c++) acc[p][c] = 0ull;

    const int gr_row = tid & (ROWS - 1);
    const int ghalf  = tid >> 7;
    constexpr int CPT = CI / 8;

    const int tx = tid % BX, ty = tid / BX;
    const int c0 = tx * TN, r0 = ty * TM;

    for (int t = 0; t < 27; t++) {
        __syncthreads();
        const float4* Wg = reinterpret_cast<const float4*>(W + (long)t * CI * CO);
        for (int i = tid; i < CI * CO / 4; i += NT)
            reinterpret_cast<float4*>(Wt)[i] = Wg[i];
        {
            const int j = jsm[gr_row * 27 + t];
#pragma unroll
            for (int cc = 0; cc < CPT; cc++) {
                const int ch = ghalf * CPT + cc;
                float4 v = make_float4(0.f, 0.f, 0.f, 0.f);
                if (j >= 0) {
                    v = reinterpret_cast<const float4*>(fin)[(long)j * (CI / 4) + ch];
                    const float4 a4 = *reinterpret_cast<const float4*>(&aS[ch * 4]);
                    const float4 b4 = *reinterpret_cast<const float4*>(&bS[ch * 4]);
                    v.x = fmaxf(fmaf(v.x, a4.x, b4.x), 0.f);
                    v.y = fmaxf(fmaf(v.y, a4.y, b4.y), 0.f);
                    v.z = fmaxf(fmaf(v.z, a4.z, b4.z), 0.f);
                    v.w = fmaxf(fmaf(v.w, a4.w, b4.w), 0.f);
                }
                const int k = ch * 4;
                featT[(k + 0) * FSTR + gr_row] = v.x;
                featT[(k + 1) * FSTR + gr_row] = v.y;
                featT[(k + 2) * FSTR + gr_row] = v.z;
                featT[(k + 3) * FSTR + gr_row] = v.w;
            }
        }
        __syncthreads();
#pragma unroll 4
        for (int k = 0; k < CI; k++) {
            unsigned long long ap[NP];
            const float* fr = &featT[k * FSTR + r0];
            if constexpr (TM == 8) {
                float4 f0 = *reinterpret_cast<const float4*>(fr);
                float4 f1 = *reinterpret_cast<const float4*>(fr + 4);
                ap[0] = pack2(f0.x, f0.y); ap[1] = pack2(f0.z, f0.w);
                ap[2] = pack2(f1.x, f1.y); ap[3] = pack2(f1.z, f1.w);
            } else if constexpr (TM == 4) {
                float4 f0 = *reinterpret_cast<const float4*>(fr);
                ap[0] = pack2(f0.x, f0.y); ap[1] = pack2(f0.z, f0.w);
            } else {
                float2 f0 = *reinterpret_cast<const float2*>(fr);
                ap[0] = pack2(f0.x, f0.y);
            }
            float4 wv = *reinterpret_cast<const float4*>(&Wt[k * CO + c0]);
            unsigned long long bw[TN] = {pack2(wv.x, wv.x), pack2(wv.y, wv.y),
                                         pack2(wv.z, wv.z), pack2(wv.w, wv.w)};
#pragma unroll
            for (int p = 0; p < NP; p++)
#pragma unroll
                for (int c = 0; c < TN; c++) ffma2(acc[p][c], ap[p], bw[c]);
        }
    }

    float psum[TN] = {0.f, 0.f, 0.f, 0.f};
    float psq [TN] = {0.f, 0.f, 0.f, 0.f};
#pragma unroll
    for (int p = 0; p < NP; p++) {
#pragma unroll
        for (int e = 0; e < 2; e++) {
            const int gr = row0 + r0 + 2 * p + e;
            if (gr < N) {
                float v[TN];
#pragma unroll
                for (int c = 0; c < TN; c++)
                    v[c] = e ? hi2(acc[p][c]) : lo2(acc[p][c]);
                *reinterpret_cast<float4*>(&fout[(long)gr * CO + c0]) =
                    make_float4(v[0], v[1], v[2], v[3]);
#pragma unroll
                for (int c = 0; c < TN; c++) {
                    psum[c] += v[c];
                    psq[c]  += v[c] * v[c];
                }
            }
        }
    }
#pragma unroll
    for (int c = 0; c < TN; c++) {
        atomicAdd(&ssum[c0 + c], psum[c]);
        atomicAdd(&ssq [c0 + c], psq[c]);
    }
    __syncthreads();
    if (tid < CO) {
        atomicAdd(&sumP[tid], ssum[tid]);
        atomicAdd(&sqP [tid], ssq[tid]);
    }
}

// ---------------------------------------------------------------------------
// Final 16 -> 3 conv, fused input-BN: one thread per row.
// ---------------------------------------------------------------------------
__global__ void __launch_bounds__(256) conv_c5_kernel(
    const float* __restrict__ fin, const int* __restrict__ nbr,
    const float* __restrict__ W, float* __restrict__ fout,
    float* __restrict__ sumP, float* __restrict__ sqP, int N,
    const float* __restrict__ pSum, const float* __restrict__ pSq,
    const float* __restrict__ pG, const float* __restrict__ pB, int pN)
{
    __shared__ float Ws[27 * 16 * 3];
    __shared__ float aSh[16], bSh[16];
    __shared__ float ss[6];
    const int tid = threadIdx.x;
    for (int i = tid; i < 27 * 48; i += 256) Ws[i] = W[i];
    if (tid < 16) {
        const float mu  = pSum[tid] / (float)pN;
        const float var = pSq[tid] / (float)pN - mu * mu;
        const float a   = pG[tid] * rsqrtf(var + 1e-3f);
        aSh[tid] = a;
        bSh[tid] = pB[tid] - mu * a;
    }
    if (tid < 6) ss[tid] = 0.f;
    __syncthreads();

    float areg[16], breg[16];
#pragma unroll
    for (int k = 0; k < 16; k++) { areg[k] = aSh[k]; breg[k] = bSh[k]; }

    const int row = blockIdx.x * 256 + tid;
    float a0 = 0.f, a1 = 0.f, a2 = 0.f;
    if (row < N) {
        for (int t = 0; t < 27; t++) {
            const int j = nbr[(long)row * 27 + t];
            if (j >= 0) {
                const float4* fr = reinterpret_cast<const float4*>(fin + (long)j * 16);
                float f[16];
                float4 q;
                q = fr[0]; f[0] = q.x; f[1] = q.y; f[2]  = q.z; f[3]  = q.w;
                q = fr[1]; f[4] = q.x; f[5] = q.y; f[6]  = q.z; f[7]  = q.w;
                q = fr[2]; f[8] = q.x; f[9] = q.y; f[10] = q.z; f[11] = q.w;
                q = fr[3]; f[12] = q.x; f[13] = q.y; f[14] = q.z; f[15] = q.w;
#pragma unroll
                for (int k = 0; k < 16; k++) {
                    const float v = fmaxf(fmaf(f[k], areg[k], breg[k]), 0.f);
                    const float* wp = &Ws[(t * 16 + k) * 3];
                    a0 += v * wp[0];
                    a1 += v * wp[1];
                    a2 += v * wp[2];
                }
            }
        }
        fout[row * 3 + 0] = a0;
        fout[row * 3 + 1] = a1;
        fout[row * 3 + 2] = a2;
    }
    atomicAdd(&ss[0], a0); atomicAdd(&ss[1], a1); atomicAdd(&ss[2], a2);
    atomicAdd(&ss[3], a0 * a0); atomicAdd(&ss[4], a1 * a1); atomicAdd(&ss[5], a2 * a2);
    __syncthreads();
    if (tid < 3) {
        atomicAdd(&sumP[tid], ss[tid]);
        atomicAdd(&sqP [tid], ss[3 + tid]);
    }
}

// ---------------------------------------------------------------------------
__global__ void normalize_kernel(const float* __restrict__ in, float* __restrict__ out,
                                 int N, int C, const float* __restrict__ g,
                                 const float* __restrict__ b,
                                 const float* __restrict__ sum,
                                 const float* __restrict__ sq)
{
    extern __shared__ float s[];
    if (threadIdx.x < C) {
        const float mu  = sum[threadIdx.x] / (float)N;
        const float var = sq[threadIdx.x] / (float)N - mu * mu;
        const float a   = g[threadIdx.x] * rsqrtf(var + 1e-3f);
        s[threadIdx.x]     = a;
        s[C + threadIdx.x] = b[threadIdx.x] - mu * a;
    }
    __syncthreads();
    const int total  = N * C;
    const int stride = gridDim.x * blockDim.x;
    for (int i = blockIdx.x * blockDim.x + threadIdx.x; i < total; i += stride) {
        const int c = i % C;
        out[i] = in[i] * s[c] + s[C + c];
    }
}

// ---------------------------------------------------------------------------

static inline int big_smem(int CO) {
    return (64 * 128 + 64 * 2 * CO + 2 * 64 + 2 * CO) * 4;
}
static inline int small_smem(int CI, int CO) {
    return (CI * FSTR + CI * CO + 2 * CI + 2 * CO) * 4 + ROWS * 27 * 4;
}

extern "C" void kernel_launch(void* const* d_in, const int* in_sizes, int n_in,
                              void* d_out, int out_size)
{
    (void)n_in;
    const long s0 = in_sizes[0], s1 = in_sizes[1];
    const bool sig = (s0 % 64 == 0) && (s1 % 27 == 0) && (s0 / 64 == s1 / 27);

    const float* x;
    const int* NB[7];   // nbr4, inv43, nbr3, inv32, nbr2, inv21, nbr1
    if (sig) {
        x = (const float*)d_in[0];
        for (int i = 0; i < 7; i++) NB[i] = (const int*)d_in[1 + i];
    } else {
        x = (const float*)d_in[7];
        for (int i = 0; i < 7; i++) NB[i] = (const int*)d_in[i];
    }
    const int n4 = (sig ? in_sizes[0] : in_sizes[7]) / 64;
    const int n3 = (sig ? in_sizes[2] : in_sizes[1]) / 27;
    const int n2 = (sig ? in_sizes[4] : in_sizes[3]) / 27;
    const int n1 = out_size / 3;

    const float *Wp[8], *Gp[8], *Bp[8];
    for (int i = 0; i < 8; i++) {
        Wp[i] = (const float*)d_in[8 + 3 * i];
        Gp[i] = (const float*)d_in[9 + 3 * i];
        Bp[i] = (const float*)d_in[10 + 3 * i];
    }

    float *bufA, *bufB, *sums, *sqs;
    cudaGetSymbolAddress((void**)&bufA, g_bufA);
    cudaGetSymbolAddress((void**)&bufB, g_bufB);
    cudaGetSymbolAddress((void**)&sums, g_sum);
    cudaGetSymbolAddress((void**)&sqs,  g_sq);

    const int smB64 = big_smem(64);   // 66560 B
    const int smB32 = big_smem(32);   // 50048 B
    cudaFuncSetAttribute(conv_big<64, false>, cudaFuncAttributeMaxDynamicSharedMemorySize, smB64);
    cudaFuncSetAttribute(conv_big<64, true >, cudaFuncAttributeMaxDynamicSharedMemorySize, smB64);
    cudaFuncSetAttribute(conv_big<32, true >, cudaFuncAttributeMaxDynamicSharedMemorySize, smB32);
    cudaFuncSetAttribute(conv_small<32, 32>, cudaFuncAttributeMaxDynamicSharedMemorySize, small_smem(32, 32));
    cudaFuncSetAttribute(conv_small<32, 16>, cudaFuncAttributeMaxDynamicSharedMemorySize, small_smem(32, 16));
    cudaFuncSetAttribute(conv_small<16, 16>, cudaFuncAttributeMaxDynamicSharedMemorySize, small_smem(16, 16));

    auto g128 = [](int n) { return (n + 127) / 128; };
    auto g256 = [](int n) { return (n + 255) / 256; };
    auto nblk = [](int total) {
        int b = (total + 255) / 256;
        return b > 16384 ? 16384 : b;
    };

    zero_stats_kernel<<<1, 256>>>();

    // L1: m4 (raw x -> bufA, n4 x 64), stats[0]
    conv_big<64, false><<<g128(n4), NT, smB64>>>(
        x, NB[0], Wp[0], bufA, sums + 0, sqs + 0, n4,
        nullptr, nullptr, nullptr, nullptr, 1);
    // L2: i4 (bn0(bufA)[n4] -> bufB, n3 x 64), stats[1]
    conv_big<64, true><<<g128(n3), NT, smB64>>>(
        bufA, NB[1], Wp[1], bufB, sums + 64, sqs + 64, n3,
        sums + 0, sqs + 0, Gp[0], Bp[0], n4);
    // L3: m3 (bn1(bufB) -> bufA, n3 x 64), stats[2]
    conv_big<64, true><<<g128(n3), NT, smB64>>>(
        bufB, NB[2], Wp[2], bufA, sums + 128, sqs + 128, n3,
        sums + 64, sqs + 64, Gp[1], Bp[1], n3);
    // L4: i3 (bn2(bufA)[n3] -> bufB, n2 x 32), stats[3]
    conv_big<32, true><<<g128(n2), NT, smB32>>>(
        bufA, NB[3], Wp[3], bufB, sums + 192, sqs + 192, n2,
        sums + 128, sqs + 128, Gp[2], Bp[2], n3);
    // L5: m2 (bn3(bufB) -> bufA, n2 x 32), stats[4]
    conv_small<32, 32><<<g128(n2), NT, small_smem(32, 32)>>>(
        bufB, NB[4], Wp[4], bufA, sums + 256, sqs + 256, n2,
        sums + 192, sqs + 192, Gp[3], Bp[3], n2);
    // L6: i2 (bn4(bufA)[n2] -> bufB, n1 x 16), stats[5]
    conv_small<32, 16><<<g128(n1), NT, small_smem(32, 16)>>>(
        bufA, NB[5], Wp[5], bufB, sums + 320, sqs + 320, n1,
        sums + 256, sqs + 256, Gp[4], Bp[4], n2);
    // L7: m1 (bn5(bufB) -> bufA, n1 x 16), stats[6]
    conv_small<16, 16><<<g128(n1), NT, small_smem(16, 16)>>>(
        bufB, NB[6], Wp[6], bufA, sums + 384, sqs + 384, n1,
        sums + 320, sqs + 320, Gp[5], Bp[5], n1);
    // L8: c5 (bn6(bufA) -> bufB, n1 x 3), stats[7]
    conv_c5_kernel<<<g256(n1), 256>>>(
        bufA, NB[6], Wp[7], bufB, sums + 448, sqs + 448, n1,
        sums + 384, sqs + 384, Gp[6], Bp[6], n1);
    // Final BN (no relu) -> d_out
    normalize_kernel<<<nblk(n1 * 3), 256, 2 * 3 * 4>>>(
        bufB, (float*)d_out, n1, 3, Gp[7], Bp[7], sums + 448, sqs + 448);
}